// round 2
// baseline (speedup 1.0000x reference)
#include <cuda_runtime.h>
#include <math.h>

constexpr int kB   = 16384;
constexpr int kM   = 64;
constexpr int kDV  = 64;
constexpr int kDK  = 64;
constexpr int kDQA = 128;
constexpr int kMV  = 4096;   // kM * kDV

// ---- scratch (device globals; no runtime allocation) ----
__device__ float g_content0[kB * kDQA];            // 8 MB
__device__ float g_w[kB * kM];                     // 4 MB
__device__ float g_mempre[(size_t)kB * kMV];       // 268 MB

__device__ __forceinline__ float sgm(float x) { return 1.0f / (1.0f + __expf(-x)); }

__device__ __forceinline__ float f4get(const float4& v, int k) {
    return k == 0 ? v.x : k == 1 ? v.y : k == 2 ? v.z : v.w;
}

// ---- packed fp32x2 helpers (sm_103a FFMA2 path) ----
typedef unsigned long long u64t;

__device__ __forceinline__ u64t pack2(float x, float y) {
    u64t r;
    asm("mov.b64 %0, {%1, %2};" : "=l"(r) : "f"(x), "f"(y));
    return r;
}
__device__ __forceinline__ void unpack2(float& x, float& y, u64t v) {
    asm("mov.b64 {%0, %1}, %2;" : "=f"(x), "=f"(y) : "l"(v));
}
__device__ __forceinline__ void ffma2(u64t& d, u64t a, u64t b) {
    asm("fma.rn.f32x2 %0, %1, %2, %3;" : "=l"(d) : "l"(a), "l"(b), "l"(d));
}

// ============================================================================
// Kernel 1: content0 = qa * sigmoid(mv_flat @ Wc0 + bc0)   (B,128)
//           write_weight = softmax(ck @ mk^T, axis=1)      (B,64)
// 128 rows / CTA, 512 threads, grid 128.
// ============================================================================
__global__ __launch_bounds__(512, 1) void k1_kernel(
    const float* __restrict__ ck, const float* __restrict__ qa,
    const float* __restrict__ mk, const float* __restrict__ mv,
    const float* __restrict__ Wc0, const float* __restrict__ bc0)
{
    extern __shared__ float sm[];
    float* As = sm;               // 128 x 68  (mv chunk / ck / logits)
    float* Bs = sm + 128 * 68;    // 64 x 132  (Wc0 chunk / mk^T)

    const int tid = threadIdx.x;
    const int tx  = tid & 15;     // 0..15
    const int ty  = tid >> 4;     // 0..31
    const int row0 = blockIdx.x * 128;

    u64t acc2[4][4];              // 4 rows x 8 cols packed as 4 pairs
#pragma unroll
    for (int i = 0; i < 4; i++)
#pragma unroll
        for (int j = 0; j < 4; j++) acc2[i][j] = 0ull;

    for (int k0 = 0; k0 < kMV; k0 += 64) {
        __syncthreads();
#pragma unroll
        for (int i = 0; i < 4; i++) {               // mv chunk: 128x64
            int e = tid + i * 512;
            int r = e >> 4, c4 = e & 15;
            *(float4*)&As[r * 68 + c4 * 4] =
                *(const float4*)&mv[(size_t)(row0 + r) * kMV + k0 + c4 * 4];
        }
#pragma unroll
        for (int i = 0; i < 4; i++) {               // Wc0 chunk: 64x128
            int e = tid + i * 512;
            int r = e >> 5, c4 = e & 31;
            *(float4*)&Bs[r * 132 + c4 * 4] =
                *(const float4*)&Wc0[(size_t)(k0 + r) * kDQA + c4 * 4];
        }
        __syncthreads();
#pragma unroll 2
        for (int k = 0; k < 64; k += 4) {
            float4 a4[4];
#pragma unroll
            for (int i = 0; i < 4; i++)
                a4[i] = *(float4*)&As[(ty * 4 + i) * 68 + k];
#pragma unroll
            for (int kk = 0; kk < 4; kk++) {
                ulonglong2 b01 = *(ulonglong2*)&Bs[(k + kk) * 132 + tx * 8];
                ulonglong2 b23 = *(ulonglong2*)&Bs[(k + kk) * 132 + tx * 8 + 4];
#pragma unroll
                for (int i = 0; i < 4; i++) {
                    float a = f4get(a4[i], kk);
                    u64t a2 = pack2(a, a);
                    ffma2(acc2[i][0], a2, b01.x);
                    ffma2(acc2[i][1], a2, b01.y);
                    ffma2(acc2[i][2], a2, b23.x);
                    ffma2(acc2[i][3], a2, b23.y);
                }
            }
        }
    }
    // content0 = qa * sigmoid(acc + bc0)
#pragma unroll
    for (int i = 0; i < 4; i++) {
        int r = row0 + ty * 4 + i;
        float accv[8];
#pragma unroll
        for (int j = 0; j < 4; j++) unpack2(accv[2 * j], accv[2 * j + 1], acc2[i][j]);
#pragma unroll
        for (int j = 0; j < 8; j++) {
            int c = tx * 8 + j;
            g_content0[r * kDQA + c] = qa[r * kDQA + c] * sgm(accv[j] + bc0[c]);
        }
    }

    // ---- write weight: logits = ck @ mk^T, softmax over m ----
    __syncthreads();
#pragma unroll
    for (int i = 0; i < 4; i++) {                   // ck tile 128x64 -> As
        int e = tid + i * 512;
        int r = e >> 4, c4 = e & 15;
        *(float4*)&As[r * 68 + c4 * 4] =
            *(const float4*)&ck[(size_t)(row0 + r) * kDK + c4 * 4];
    }
#pragma unroll
    for (int i = 0; i < 8; i++) {                   // mk transposed -> Bs[k][m]
        int e = tid + i * 512;
        int m_ = e >> 6, kk = e & 63;
        Bs[kk * 68 + m_] = mk[m_ * kDK + kk];
    }
    __syncthreads();
    u64t lg2[4][2];
#pragma unroll
    for (int i = 0; i < 4; i++) { lg2[i][0] = 0ull; lg2[i][1] = 0ull; }
#pragma unroll 4
    for (int k = 0; k < 64; k++) {
        ulonglong2 b = *(ulonglong2*)&Bs[k * 68 + tx * 4];
#pragma unroll
        for (int i = 0; i < 4; i++) {
            float a = As[(ty * 4 + i) * 68 + k];
            u64t a2 = pack2(a, a);
            ffma2(lg2[i][0], a2, b.x);
            ffma2(lg2[i][1], a2, b.y);
        }
    }
    __syncthreads();
#pragma unroll
    for (int i = 0; i < 4; i++) {
        float l0, l1, l2, l3;
        unpack2(l0, l1, lg2[i][0]);
        unpack2(l2, l3, lg2[i][1]);
        As[(ty * 4 + i) * 68 + tx * 4 + 0] = l0;
        As[(ty * 4 + i) * 68 + tx * 4 + 1] = l1;
        As[(ty * 4 + i) * 68 + tx * 4 + 2] = l2;
        As[(ty * 4 + i) * 68 + tx * 4 + 3] = l3;
    }
    __syncthreads();
    if (tid < 128) {
        int r = tid;
        float mx = -1e30f;
        for (int m_ = 0; m_ < kM; m_++) mx = fmaxf(mx, As[r * 68 + m_]);
        float s = 0.f;
        for (int m_ = 0; m_ < kM; m_++) {
            float e = __expf(As[r * 68 + m_] - mx);
            As[r * 68 + m_] = e; s += e;
        }
        float inv = 1.f / s;
        for (int m_ = 0; m_ < kM; m_++)
            g_w[(row0 + r) * kM + m_] = As[r * 68 + m_] * inv;
    }
}

// ============================================================================
// Kernel 2: everything else, fused per 128-row tile.
// ============================================================================
__global__ __launch_bounds__(512, 1) void k2_kernel(
    const float* __restrict__ mv,
    const float* __restrict__ We,   const float* __restrict__ be,
    const float* __restrict__ Wemv, const float* __restrict__ bemv,
    const float* __restrict__ Wza,  const float* __restrict__ bza,
    const float* __restrict__ Wamv, const float* __restrict__ bamv,
    const float* __restrict__ Wm1,  const float* __restrict__ bm1,
    const float* __restrict__ Wz,   const float* __restrict__ bz,
    const float* __restrict__ Wzmv, const float* __restrict__ bzmv,
    float* __restrict__ out)
{
    extern __shared__ float sm[];
    float* c0s  = sm;                   // 128 x 132 : content0 tile
    float* bufA = c0s + 128 * 132;      // 128 x 68  : Wm1 chunk / We / Wz / add
    float* buf3 = bufA + 128 * 68;      // 3 x 64 x 68: W*mv chunks / erase+Wza
    float* bufM = buf3 + 3 * 64 * 68;   // 128 x 68  : memory_pre chunk / zt

    const int tid = threadIdx.x;
    const int tx  = tid & 15;
    const int ty  = tid >> 4;
    const int row0 = blockIdx.x * 128;
    const int col  = tx * 4;

#pragma unroll
    for (int i = 0; i < 8; i++) {                   // content0 tile 128x128
        int e = tid + i * 512;
        int r = e >> 5, c4 = e & 31;
        *(float4*)&c0s[r * 132 + c4 * 4] =
            *(const float4*)&g_content0[(size_t)(row0 + r) * kDQA + c4 * 4];
    }

    u64t acce2[4][2], accz2[4][2], acca2[4][2];
#pragma unroll
    for (int i = 0; i < 4; i++)
#pragma unroll
        for (int p = 0; p < 2; p++) { acce2[i][p] = 0ull; accz2[i][p] = 0ull; acca2[i][p] = 0ull; }

    for (int mch = 0; mch < kM; mch++) {
#pragma unroll
        for (int i = 0; i < 4; i++) {               // Wm1[:, chunk] 128x64
            int e = tid + i * 512;
            int r = e >> 4, c4 = e & 15;
            *(float4*)&bufA[r * 68 + c4 * 4] =
                *(const float4*)&Wm1[(size_t)r * kMV + mch * 64 + c4 * 4];
        }
#pragma unroll
        for (int i = 0; i < 2; i++) {               // W*mv[chunk,:] 64x64 each
            int e = tid + i * 512;
            int r = e >> 4, c4 = e & 15;
            size_t g = (size_t)(mch * 64 + r) * kDV + c4 * 4;
            *(float4*)&buf3[              r * 68 + c4 * 4] = *(const float4*)&Wemv[g];
            *(float4*)&buf3[64 * 68   +   r * 68 + c4 * 4] = *(const float4*)&Wzmv[g];
            *(float4*)&buf3[2 * 64 * 68 + r * 68 + c4 * 4] = *(const float4*)&Wamv[g];
        }
        __syncthreads();

        // g1pre = c0 @ Wm1chunk  (128x64, K=128)
        u64t a1_2[4][2];
#pragma unroll
        for (int i = 0; i < 4; i++) { a1_2[i][0] = 0ull; a1_2[i][1] = 0ull; }
#pragma unroll 2
        for (int k = 0; k < kDQA; k += 4) {
            float4 a4[4];
#pragma unroll
            for (int i = 0; i < 4; i++)
                a4[i] = *(float4*)&c0s[(ty * 4 + i) * 132 + k];
#pragma unroll
            for (int kk = 0; kk < 4; kk++) {
                ulonglong2 b = *(ulonglong2*)&bufA[(k + kk) * 68 + col];
#pragma unroll
                for (int i = 0; i < 4; i++) {
                    float a = f4get(a4[i], kk);
                    u64t a2 = pack2(a, a);
                    ffma2(a1_2[i][0], a2, b.x);
                    ffma2(a1_2[i][1], a2, b.y);
                }
            }
        }
        float bm[4];
#pragma unroll
        for (int j = 0; j < 4; j++) bm[j] = bm1[mch * 64 + col + j];
#pragma unroll
        for (int i = 0; i < 4; i++) {
            int r = row0 + ty * 4 + i;
            float4 m4 = *(const float4*)&mv[(size_t)r * kMV + mch * 64 + col];
            float g0, g1, g2, g3;
            unpack2(g0, g1, a1_2[i][0]);
            unpack2(g2, g3, a1_2[i][1]);
            float4 mp;
            mp.x = m4.x * sgm(g0 + bm[0]);
            mp.y = m4.y * sgm(g1 + bm[1]);
            mp.z = m4.z * sgm(g2 + bm[2]);
            mp.w = m4.w * sgm(g3 + bm[3]);
            *(float4*)&bufM[(ty * 4 + i) * 68 + col] = mp;
            *(float4*)&g_mempre[(size_t)r * kMV + mch * 64 + col] = mp;
        }
        __syncthreads();

        // accumulate the three K=4096 reductions
#pragma unroll 2
        for (int k = 0; k < 64; k += 4) {
            float4 a4[4];
#pragma unroll
            for (int i = 0; i < 4; i++)
                a4[i] = *(float4*)&bufM[(ty * 4 + i) * 68 + k];
#pragma unroll
            for (int kk = 0; kk < 4; kk++) {
                ulonglong2 eb = *(ulonglong2*)&buf3[              (k + kk) * 68 + col];
                ulonglong2 zb = *(ulonglong2*)&buf3[64 * 68   +   (k + kk) * 68 + col];
                ulonglong2 ab = *(ulonglong2*)&buf3[2 * 64 * 68 + (k + kk) * 68 + col];
#pragma unroll
                for (int i = 0; i < 4; i++) {
                    float a = f4get(a4[i], kk);
                    u64t a2 = pack2(a, a);
                    ffma2(acce2[i][0], a2, eb.x);
                    ffma2(acce2[i][1], a2, eb.y);
                    ffma2(accz2[i][0], a2, zb.x);
                    ffma2(accz2[i][1], a2, zb.y);
                    ffma2(acca2[i][0], a2, ab.x);
                    ffma2(acca2[i][1], a2, ab.y);
                }
            }
        }
        __syncthreads();
    }

    // ---- e1pre = c0 @ We ----
#pragma unroll
    for (int i = 0; i < 4; i++) {
        int e = tid + i * 512;
        int r = e >> 4, c4 = e & 15;
        *(float4*)&bufA[r * 68 + c4 * 4] = *(const float4*)&We[(size_t)r * kDV + c4 * 4];
    }
    __syncthreads();
    u64t e1p2[4][2];
#pragma unroll
    for (int i = 0; i < 4; i++) { e1p2[i][0] = 0ull; e1p2[i][1] = 0ull; }
#pragma unroll 2
    for (int k = 0; k < kDQA; k += 4) {
        float4 a4[4];
#pragma unroll
        for (int i = 0; i < 4; i++) a4[i] = *(float4*)&c0s[(ty * 4 + i) * 132 + k];
#pragma unroll
        for (int kk = 0; kk < 4; kk++) {
            ulonglong2 b = *(ulonglong2*)&bufA[(k + kk) * 68 + col];
#pragma unroll
            for (int i = 0; i < 4; i++) {
                float a = f4get(a4[i], kk);
                u64t a2 = pack2(a, a);
                ffma2(e1p2[i][0], a2, b.x);
                ffma2(e1p2[i][1], a2, b.y);
            }
        }
    }
    __syncthreads();
    // ---- zcpre = c0 @ Wz ----
#pragma unroll
    for (int i = 0; i < 4; i++) {
        int e = tid + i * 512;
        int r = e >> 4, c4 = e & 15;
        *(float4*)&bufA[r * 68 + c4 * 4] = *(const float4*)&Wz[(size_t)r * kDV + c4 * 4];
    }
    __syncthreads();
    u64t zcp2[4][2];
#pragma unroll
    for (int i = 0; i < 4; i++) { zcp2[i][0] = 0ull; zcp2[i][1] = 0ull; }
#pragma unroll 2
    for (int k = 0; k < kDQA; k += 4) {
        float4 a4[4];
#pragma unroll
        for (int i = 0; i < 4; i++) a4[i] = *(float4*)&c0s[(ty * 4 + i) * 132 + k];
#pragma unroll
        for (int kk = 0; kk < 4; kk++) {
            ulonglong2 b = *(ulonglong2*)&bufA[(k + kk) * 68 + col];
#pragma unroll
            for (int i = 0; i < 4; i++) {
                float a = f4get(a4[i], kk);
                u64t a2 = pack2(a, a);
                ffma2(zcp2[i][0], a2, b.x);
                ffma2(zcp2[i][1], a2, b.y);
            }
        }
    }

    // erase -> buf3[0:8704], zt -> bufM
    float bev[4], bemvv[4], bzv[4], bzmvv[4];
#pragma unroll
    for (int j = 0; j < 4; j++) {
        bev[j] = be[col + j]; bemvv[j] = bemv[col + j];
        bzv[j] = bz[col + j]; bzmvv[j] = bzmv[col + j];
    }
#pragma unroll
    for (int i = 0; i < 4; i++) {
        int lr = ty * 4 + i;
        float e1p[4], zcp[4], acce[4], accz[4];
        unpack2(e1p[0], e1p[1], e1p2[i][0]);  unpack2(e1p[2], e1p[3], e1p2[i][1]);
        unpack2(zcp[0], zcp[1], zcp2[i][0]);  unpack2(zcp[2], zcp[3], zcp2[i][1]);
        unpack2(acce[0], acce[1], acce2[i][0]); unpack2(acce[2], acce[3], acce2[i][1]);
        unpack2(accz[0], accz[1], accz2[i][0]); unpack2(accz[2], accz[3], accz2[i][1]);
#pragma unroll
        for (int j = 0; j < 4; j++) {
            float er = sgm(sgm(e1p[j] + bev[j]) + sgm(acce[j] + bemvv[j]));
            buf3[lr * 68 + col + j] = er;
            float zt = sgm(zcp[j] + bzv[j] + accz[j] + bzmvv[j]);
            bufM[lr * 68 + col + j] = zt;
        }
    }
    __syncthreads();
    // stage Wza at buf3 + 8704
#pragma unroll
    for (int i = 0; i < 2; i++) {
        int e = tid + i * 512;
        int r = e >> 4, c4 = e & 15;
        *(float4*)&buf3[8704 + r * 68 + c4 * 4] =
            *(const float4*)&Wza[(size_t)r * kDV + c4 * 4];
    }
    __syncthreads();
    // tapre = zt @ Wza  (K=64)
    u64t tap2[4][2];
#pragma unroll
    for (int i = 0; i < 4; i++) { tap2[i][0] = 0ull; tap2[i][1] = 0ull; }
#pragma unroll 2
    for (int k = 0; k < 64; k += 4) {
        float4 a4[4];
#pragma unroll
        for (int i = 0; i < 4; i++) a4[i] = *(float4*)&bufM[(ty * 4 + i) * 68 + k];
#pragma unroll
        for (int kk = 0; kk < 4; kk++) {
            ulonglong2 b = *(ulonglong2*)&buf3[8704 + (k + kk) * 68 + col];
#pragma unroll
            for (int i = 0; i < 4; i++) {
                float a = f4get(a4[i], kk);
                u64t a2 = pack2(a, a);
                ffma2(tap2[i][0], a2, b.x);
                ffma2(tap2[i][1], a2, b.y);
            }
        }
    }
    float bzav[4], bamvv[4];
#pragma unroll
    for (int j = 0; j < 4; j++) { bzav[j] = bza[col + j]; bamvv[j] = bamv[col + j]; }
#pragma unroll
    for (int i = 0; i < 4; i++) {
        int lr = ty * 4 + i;
        float tap[4], acca[4];
        unpack2(tap[0], tap[1], tap2[i][0]);  unpack2(tap[2], tap[3], tap2[i][1]);
        unpack2(acca[0], acca[1], acca2[i][0]); unpack2(acca[2], acca[3], acca2[i][1]);
#pragma unroll
        for (int j = 0; j < 4; j++) {
            float ad = tanhf(tanhf(tap[j] + bzav[j]) + tanhf(acca[j] + bamvv[j]));
            bufA[lr * 68 + col + j] = ad;   // add signal
        }
    }
    __syncthreads();

    // ---- final combine: out = mempre*(1 - w*erase) + w*add ----
    float4 e4[4], a4f[4];
#pragma unroll
    for (int i = 0; i < 4; i++) {
        e4[i]  = *(float4*)&buf3[(ty * 4 + i) * 68 + col];
        a4f[i] = *(float4*)&bufA[(ty * 4 + i) * 68 + col];
    }
    for (int mm = 0; mm < kM; mm++) {
#pragma unroll
        for (int i = 0; i < 4; i++) {
            int r = row0 + ty * 4 + i;
            float w = g_w[r * kM + mm];
            float4 mp = *(float4*)&g_mempre[(size_t)r * kMV + mm * 64 + col];
            float4 o;
            o.x = mp.x * (1.f - w * e4[i].x) + w * a4f[i].x;
            o.y = mp.y * (1.f - w * e4[i].y) + w * a4f[i].y;
            o.z = mp.z * (1.f - w * e4[i].z) + w * a4f[i].z;
            o.w = mp.w * (1.f - w * e4[i].w) + w * a4f[i].w;
            *(float4*)&out[(size_t)r * kMV + mm * 64 + col] = o;
        }
    }
}

extern "C" void kernel_launch(void* const* d_in, const int* in_sizes, int n_in,
                              void* d_out, int out_size)
{
    const float* ck   = (const float*)d_in[0];
    const float* qa   = (const float*)d_in[1];
    const float* mk   = (const float*)d_in[2];
    const float* mv   = (const float*)d_in[3];
    const float* We   = (const float*)d_in[4];
    const float* be   = (const float*)d_in[5];
    const float* Wemv = (const float*)d_in[6];
    const float* bemv = (const float*)d_in[7];
    const float* Wza  = (const float*)d_in[8];
    const float* bza  = (const float*)d_in[9];
    const float* Wamv = (const float*)d_in[10];
    const float* bamv = (const float*)d_in[11];
    const float* Wc0  = (const float*)d_in[12];
    const float* bc0  = (const float*)d_in[13];
    const float* Wm1  = (const float*)d_in[14];
    const float* bm1  = (const float*)d_in[15];
    const float* Wz   = (const float*)d_in[16];
    const float* bz   = (const float*)d_in[17];
    const float* Wzmv = (const float*)d_in[18];
    const float* bzmv = (const float*)d_in[19];

    const int smem1 = (128 * 68 + 64 * 132) * 4;                           // 68608
    const int smem2 = (128 * 132 + 128 * 68 + 3 * 64 * 68 + 128 * 68) * 4; // 189440
    cudaFuncSetAttribute(k1_kernel, cudaFuncAttributeMaxDynamicSharedMemorySize, smem1);
    cudaFuncSetAttribute(k2_kernel, cudaFuncAttributeMaxDynamicSharedMemorySize, smem2);

    k1_kernel<<<kB / 128, 512, smem1>>>(ck, qa, mk, mv, Wc0, bc0);
    k2_kernel<<<kB / 128, 512, smem2>>>(mv, We, be, Wemv, bemv, Wza, bza,
                                        Wamv, bamv, Wm1, bm1, Wz, bz,
                                        Wzmv, bzmv, (float*)d_out);
}

// round 7
// speedup vs baseline: 2.3607x; 2.3607x over previous
#include <cuda_runtime.h>
#include <cuda_bf16.h>
#include <math.h>

constexpr int kB   = 16384;
constexpr int kM   = 64;
constexpr int kDV  = 64;
constexpr int kDK  = 64;
constexpr int kDQA = 128;
constexpr int kMV  = 4096;   // kM * kDV

// ---- device-global scratch (no runtime allocation) ----
__device__ float g_w[kB * kM];                         // 4 MB
__device__ float g_mempre[(size_t)kB * kMV];           // 268 MB
__device__ __nv_bfloat16 g_c0h[kB * kDQA], g_c0l[kB * kDQA];      // 4+4 MB
__device__ __nv_bfloat16 g_Wc0h[kMV * kDQA],  g_Wc0l[kMV * kDQA];
__device__ __nv_bfloat16 g_Wm1h[kDQA * kMV],  g_Wm1l[kDQA * kMV];
__device__ __nv_bfloat16 g_Wemvh[kMV * kDV],  g_Wemvl[kMV * kDV];
__device__ __nv_bfloat16 g_Wzmvh[kMV * kDV],  g_Wzmvl[kMV * kDV];
__device__ __nv_bfloat16 g_Wamvh[kMV * kDV],  g_Wamvl[kMV * kDV];
__device__ __nv_bfloat16 g_Weh[kDQA * kDV],   g_Wel[kDQA * kDV];
__device__ __nv_bfloat16 g_Wzh[kDQA * kDV],   g_Wzl[kDQA * kDV];
__device__ __nv_bfloat16 g_Wzah[kDV * kDV],   g_Wzal[kDV * kDV];

__device__ __forceinline__ float sgm(float x) { return 1.0f / (1.0f + __expf(-x)); }

__device__ __forceinline__ void splitf(float x, __nv_bfloat16& h, __nv_bfloat16& l) {
    h = __float2bfloat16_rn(x);
    l = __float2bfloat16_rn(x - __bfloat162float(h));
}

__device__ __forceinline__ unsigned smaddr(const void* p) {
    return (unsigned)__cvta_generic_to_shared(p);
}

__device__ __forceinline__ void ldsm4(unsigned r[4], unsigned a) {
    asm volatile("ldmatrix.sync.aligned.m8n8.x4.shared.b16 {%0,%1,%2,%3}, [%4];"
        : "=r"(r[0]), "=r"(r[1]), "=r"(r[2]), "=r"(r[3]) : "r"(a));
}
__device__ __forceinline__ void ldsm4t(unsigned r[4], unsigned a) {
    asm volatile("ldmatrix.sync.aligned.m8n8.x4.trans.shared.b16 {%0,%1,%2,%3}, [%4];"
        : "=r"(r[0]), "=r"(r[1]), "=r"(r[2]), "=r"(r[3]) : "r"(a));
}
__device__ __forceinline__ void mma16816(float* c, const unsigned* a, const unsigned* b) {
    asm volatile(
        "mma.sync.aligned.m16n8k16.row.col.f32.bf16.bf16.f32 "
        "{%0,%1,%2,%3}, {%4,%5,%6,%7}, {%8,%9}, {%0,%1,%2,%3};"
        : "+f"(c[0]), "+f"(c[1]), "+f"(c[2]), "+f"(c[3])
        : "r"(a[0]), "r"(a[1]), "r"(a[2]), "r"(a[3]), "r"(b[0]), "r"(b[1]));
}

// GEMM core: C (NPAIR*2 n8-tiles, 16 rows) += split(A) @ split(B), K = KSTEPS*16.
// aH/aL: byte addr of A hi/lo base incl. per-lane offsets ((lane%16)*lda + (lane/16)*16B).
// bH/bL: byte addr of B hi/lo base incl. ((lane%16)*ldbB + n0*2 + (lane/16)*16B).
template<int NPAIR, int KSTEPS>
__device__ __forceinline__ void mma_gemm(float* c, unsigned aH, unsigned aL,
                                         unsigned bH, unsigned bL, int ldbB) {
#pragma unroll
    for (int ks = 0; ks < KSTEPS; ks++) {
        unsigned ah[4], al[4];
        ldsm4(ah, aH + ks * 32);
        ldsm4(al, aL + ks * 32);
#pragma unroll
        for (int p = 0; p < NPAIR; p++) {
            unsigned bh[4], bl[4];
            ldsm4t(bh, bH + ks * 16 * ldbB + p * 32);
            ldsm4t(bl, bL + ks * 16 * ldbB + p * 32);
#pragma unroll
            for (int h = 0; h < 2; h++) {
                float* ct = c + (p * 2 + h) * 4;
                mma16816(ct, ah, &bh[h * 2]);
                mma16816(ct, ah, &bl[h * 2]);
                mma16816(ct, al, &bh[h * 2]);
            }
        }
    }
}

// ============================================================================
// k0: split all weights into hi/lo bf16 (runs every launch; deterministic)
// ============================================================================
__global__ void k0_convert(const float* __restrict__ Wc0, const float* __restrict__ Wm1,
                           const float* __restrict__ Wemv, const float* __restrict__ Wzmv,
                           const float* __restrict__ Wamv, const float* __restrict__ We,
                           const float* __restrict__ Wz,   const float* __restrict__ Wza)
{
    int i = blockIdx.x * blockDim.x + threadIdx.x;
    if (i < kMV * kDQA) {
        splitf(Wc0[i], g_Wc0h[i], g_Wc0l[i]);
        splitf(Wm1[i], g_Wm1h[i], g_Wm1l[i]);
    }
    if (i < kMV * kDV) {
        splitf(Wemv[i], g_Wemvh[i], g_Wemvl[i]);
        splitf(Wzmv[i], g_Wzmvh[i], g_Wzmvl[i]);
        splitf(Wamv[i], g_Wamvh[i], g_Wamvl[i]);
    }
    if (i < kDQA * kDV) {
        splitf(We[i], g_Weh[i], g_Wel[i]);
        splitf(Wz[i], g_Wzh[i], g_Wzl[i]);
    }
    if (i < kDV * kDV) splitf(Wza[i], g_Wzah[i], g_Wzal[i]);
}

// ============================================================================
// k1: c0 = qa * sigmoid(mv_flat @ Wc0 + bc0)  -> g_c0h/g_c0l
//     write_weight = softmax(ck @ mk^T)       -> g_w
// 128 rows/CTA, 512 threads (16 warps as 8 row-groups x 2 col-groups of 64).
// smem (f32 words): mvh[0]=4608, mvl[4608], wch[9216]=4352, wcl[13568]; tot 17920
// ============================================================================
__global__ __launch_bounds__(512, 1) void k1_kernel(
    const float* __restrict__ ck, const float* __restrict__ qa,
    const float* __restrict__ mk, const float* __restrict__ mv,
    const float* __restrict__ bc0)
{
    extern __shared__ float sm[];
    __nv_bfloat16* mvh = (__nv_bfloat16*)(sm + 0);       // [128][72]
    __nv_bfloat16* mvl = (__nv_bfloat16*)(sm + 4608);
    __nv_bfloat16* wch = (__nv_bfloat16*)(sm + 9216);    // [64][136]
    __nv_bfloat16* wcl = (__nv_bfloat16*)(sm + 13568);

    const int tid  = threadIdx.x;
    const int lane = tid & 31;
    const int w    = tid >> 5;
    const int wr   = w & 7;        // row group (16 rows)
    const int wc   = w >> 3;       // col group (64 cols)
    const int row0 = blockIdx.x * 128;
    const int lr   = lane & 15, lcc = lane >> 4;

    float acc[32];
#pragma unroll
    for (int i = 0; i < 32; i++) acc[i] = 0.f;

    const unsigned aH = smaddr(&mvh[(wr * 16 + lr) * 72 + lcc * 8]);
    const unsigned aL = smaddr(&mvl[(wr * 16 + lr) * 72 + lcc * 8]);
    const unsigned bH = smaddr(&wch[lr * 136 + wc * 64 + lcc * 8]);
    const unsigned bL = smaddr(&wcl[lr * 136 + wc * 64 + lcc * 8]);

    for (int k0c = 0; k0c < kMV; k0c += 64) {
        __syncthreads();
#pragma unroll
        for (int i = 0; i < 4; i++) {                    // mv 128x64 f32 -> hi/lo
            int e = tid + i * 512;
            int r = e >> 4, c4 = e & 15;
            float4 v = *(const float4*)&mv[(size_t)(row0 + r) * kMV + k0c + c4 * 4];
            __nv_bfloat16 h0,l0,h1,l1,h2,l2,h3,l3;
            splitf(v.x,h0,l0); splitf(v.y,h1,l1); splitf(v.z,h2,l2); splitf(v.w,h3,l3);
            __nv_bfloat162 t;
            t.x=h0; t.y=h1; *(__nv_bfloat162*)&mvh[r*72 + c4*4    ] = t;
            t.x=h2; t.y=h3; *(__nv_bfloat162*)&mvh[r*72 + c4*4 + 2] = t;
            t.x=l0; t.y=l1; *(__nv_bfloat162*)&mvl[r*72 + c4*4    ] = t;
            t.x=l2; t.y=l3; *(__nv_bfloat162*)&mvl[r*72 + c4*4 + 2] = t;
        }
#pragma unroll
        for (int i = 0; i < 2; i++) {                    // Wc0 chunk 64x128 bf16
            int e = tid + i * 512;
            int r = e >> 4, c = (e & 15) * 8;
            *(uint4*)&wch[r * 136 + c] = *(const uint4*)&g_Wc0h[(size_t)(k0c + r) * kDQA + c];
            *(uint4*)&wcl[r * 136 + c] = *(const uint4*)&g_Wc0l[(size_t)(k0c + r) * kDQA + c];
        }
        __syncthreads();
        mma_gemm<4, 4>(acc, aH, aL, bH, bL, 272);
    }

    // epilogue: c0 = qa * sigmoid(acc + bc0) -> g_c0h/l
#pragma unroll
    for (int t = 0; t < 8; t++) {
        int c = wc * 64 + t * 8 + 2 * (lane & 3);
        float b0 = bc0[c], b1 = bc0[c + 1];
#pragma unroll
        for (int half = 0; half < 2; half++) {
            int r = row0 + wr * 16 + (lane >> 2) + half * 8;
            float2 q = *(const float2*)&qa[(size_t)r * kDQA + c];
            float o0 = q.x * sgm(acc[t * 4 + half * 2 + 0] + b0);
            float o1 = q.y * sgm(acc[t * 4 + half * 2 + 1] + b1);
            __nv_bfloat16 h0,l0,h1,l1;
            splitf(o0, h0, l0); splitf(o1, h1, l1);
            __nv_bfloat162 ph; ph.x = h0; ph.y = h1;
            __nv_bfloat162 pl; pl.x = l0; pl.y = l1;
            *(__nv_bfloat162*)&g_c0h[(size_t)r * kDQA + c] = ph;
            *(__nv_bfloat162*)&g_c0l[(size_t)r * kDQA + c] = pl;
        }
    }

    // ---- write weight: logits = ck @ mk^T, softmax over m (scalar; tiny) ----
    __syncthreads();
    float* As = sm;            // [128][68]  (reuse mv region: 9216 words)
    float* Bs = sm + 9216;     // [64][68]   (reuse Wc0 region)
    const int tx = tid & 15, ty = tid >> 4;
#pragma unroll
    for (int i = 0; i < 4; i++) {                        // ck tile 128x64
        int e = tid + i * 512;
        int r = e >> 4, c4 = e & 15;
        *(float4*)&As[r * 68 + c4 * 4] =
            *(const float4*)&ck[(size_t)(row0 + r) * kDK + c4 * 4];
    }
#pragma unroll
    for (int i = 0; i < 8; i++) {                        // mk transposed Bs[k][m]
        int e = tid + i * 512;
        int m_ = e >> 6, kk = e & 63;
        Bs[kk * 68 + m_] = mk[m_ * kDK + kk];
    }
    __syncthreads();
    float lg[4][4];
#pragma unroll
    for (int i = 0; i < 4; i++)
#pragma unroll
        for (int j = 0; j < 4; j++) lg[i][j] = 0.f;
#pragma unroll 4
    for (int k = 0; k < 64; k++) {
        float a[4];
#pragma unroll
        for (int i = 0; i < 4; i++) a[i] = As[(ty * 4 + i) * 68 + k];
        float4 b = *(float4*)&Bs[k * 68 + tx * 4];
#pragma unroll
        for (int i = 0; i < 4; i++) {
            lg[i][0] += a[i] * b.x; lg[i][1] += a[i] * b.y;
            lg[i][2] += a[i] * b.z; lg[i][3] += a[i] * b.w;
        }
    }
    __syncthreads();
#pragma unroll
    for (int i = 0; i < 4; i++)
#pragma unroll
        for (int j = 0; j < 4; j++)
            As[(ty * 4 + i) * 68 + tx * 4 + j] = lg[i][j];
    __syncthreads();
    if (tid < 128) {
        int r = tid;
        float mx = -1e30f;
        for (int m_ = 0; m_ < kM; m_++) mx = fmaxf(mx, As[r * 68 + m_]);
        float s = 0.f;
        for (int m_ = 0; m_ < kM; m_++) {
            float e = __expf(As[r * 68 + m_] - mx);
            As[r * 68 + m_] = e; s += e;
        }
        float inv = 1.f / s;
        for (int m_ = 0; m_ < kM; m_++)
            g_w[(row0 + r) * kM + m_] = As[r * 68 + m_] * inv;
    }
}

// ============================================================================
// k2: gate1/memory_pre, three mv-reductions, erase/zt/add, final combine.
// 16 warps as 8 row-groups x 2 col-groups of 32.
// smem layout (f32 words):
//   c0h 0      (8704)   c0l 8704   (8704)      [128][136] bf16
//   mph 17408  (4608)   mpl 22016  (4608)      [128][72]  bf16   (also zt)
//   wm1h 26624 (4608)   wm1l 31232 (4608)      [128][72]  bf16   (also We; then erase f32 [128][68])
//   w3   35840 (13824): emvh/emvl/zmvh/zmvl/amvh/amvl [64][72] each (2304)
//        (then: Wzh/Wzl [128][72] at 35840/40448; Wzah/Wzal [64][72] at 45056/47360;
//         add f32 [128][68] at 35840)
//   total 49664 words = 198656 B
// ============================================================================
__global__ __launch_bounds__(512, 1) void k2_kernel(
    const float* __restrict__ mv,
    const float* __restrict__ be,   const float* __restrict__ bemv,
    const float* __restrict__ bza,  const float* __restrict__ bamv,
    const float* __restrict__ bm1,  const float* __restrict__ bz,
    const float* __restrict__ bzmv, float* __restrict__ out)
{
    extern __shared__ float sm[];
    __nv_bfloat16* c0h  = (__nv_bfloat16*)(sm + 0);
    __nv_bfloat16* c0l  = (__nv_bfloat16*)(sm + 8704);
    __nv_bfloat16* mph  = (__nv_bfloat16*)(sm + 17408);
    __nv_bfloat16* mpl  = (__nv_bfloat16*)(sm + 22016);
    __nv_bfloat16* wm1h = (__nv_bfloat16*)(sm + 26624);
    __nv_bfloat16* wm1l = (__nv_bfloat16*)(sm + 31232);
    __nv_bfloat16* emvh = (__nv_bfloat16*)(sm + 35840);
    __nv_bfloat16* emvl = (__nv_bfloat16*)(sm + 35840 + 2304);
    __nv_bfloat16* zmvh = (__nv_bfloat16*)(sm + 35840 + 4608);
    __nv_bfloat16* zmvl = (__nv_bfloat16*)(sm + 35840 + 6912);
    __nv_bfloat16* amvh = (__nv_bfloat16*)(sm + 35840 + 9216);
    __nv_bfloat16* amvl = (__nv_bfloat16*)(sm + 35840 + 11520);
    __nv_bfloat16* wzh  = (__nv_bfloat16*)(sm + 35840);          // [128][72]
    __nv_bfloat16* wzl  = (__nv_bfloat16*)(sm + 40448);
    __nv_bfloat16* zah  = (__nv_bfloat16*)(sm + 45056);          // [64][72]
    __nv_bfloat16* zal  = (__nv_bfloat16*)(sm + 47360);
    float* es = sm + 26624;   // erase f32 [128][68]
    float* ad = sm + 35840;   // add   f32 [128][68]

    const int tid  = threadIdx.x;
    const int lane = tid & 31;
    const int w    = tid >> 5;
    const int wr   = w & 7;
    const int wc   = w >> 3;
    const int row0 = blockIdx.x * 128;
    const int lr   = lane & 15, lcc = lane >> 4;

    // load c0 tiles (hi/lo)
#pragma unroll
    for (int i = 0; i < 4; i++) {
        int e = tid + i * 512;
        int r = e >> 4, c = (e & 15) * 8;
        *(uint4*)&c0h[r * 136 + c] = *(const uint4*)&g_c0h[(size_t)(row0 + r) * kDQA + c];
        *(uint4*)&c0l[r * 136 + c] = *(const uint4*)&g_c0l[(size_t)(row0 + r) * kDQA + c];
    }

    // per-lane operand bases
    const unsigned aC0H = smaddr(&c0h[(wr * 16 + lr) * 136 + lcc * 8]);
    const unsigned aC0L = smaddr(&c0l[(wr * 16 + lr) * 136 + lcc * 8]);
    const unsigned aMPH = smaddr(&mph[(wr * 16 + lr) * 72 + lcc * 8]);
    const unsigned aMPL = smaddr(&mpl[(wr * 16 + lr) * 72 + lcc * 8]);
    const int bcol = wc * 32 + lcc * 8;
    const unsigned bWm1H = smaddr(&wm1h[lr * 72 + bcol]);
    const unsigned bWm1L = smaddr(&wm1l[lr * 72 + bcol]);
    const unsigned bEmvH = smaddr(&emvh[lr * 72 + bcol]);
    const unsigned bEmvL = smaddr(&emvl[lr * 72 + bcol]);
    const unsigned bZmvH = smaddr(&zmvh[lr * 72 + bcol]);
    const unsigned bZmvL = smaddr(&zmvl[lr * 72 + bcol]);
    const unsigned bAmvH = smaddr(&amvh[lr * 72 + bcol]);
    const unsigned bAmvL = smaddr(&amvl[lr * 72 + bcol]);
    const unsigned bWzH  = smaddr(&wzh[lr * 72 + bcol]);
    const unsigned bWzL  = smaddr(&wzl[lr * 72 + bcol]);
    const unsigned bZaH  = smaddr(&zah[lr * 72 + bcol]);
    const unsigned bZaL  = smaddr(&zal[lr * 72 + bcol]);

    float acce[16], accz[16], acca[16];
#pragma unroll
    for (int i = 0; i < 16; i++) { acce[i] = 0.f; accz[i] = 0.f; acca[i] = 0.f; }

    for (int mch = 0; mch < kM; mch++) {
        __syncthreads();
#pragma unroll
        for (int i = 0; i < 2; i++) {                    // Wm1 chunk [128][64]
            int e = tid + i * 512;
            int r = e >> 3, c = (e & 7) * 8;
            *(uint4*)&wm1h[r * 72 + c] = *(const uint4*)&g_Wm1h[(size_t)r * kMV + mch * 64 + c];
            *(uint4*)&wm1l[r * 72 + c] = *(const uint4*)&g_Wm1l[(size_t)r * kMV + mch * 64 + c];
        }
        {                                                // W*mv chunks [64][64]
            int r = tid >> 3, c = (tid & 7) * 8;
            size_t g = (size_t)(mch * 64 + r) * kDV + c;
            *(uint4*)&emvh[r * 72 + c] = *(const uint4*)&g_Wemvh[g];
            *(uint4*)&emvl[r * 72 + c] = *(const uint4*)&g_Wemvl[g];
            *(uint4*)&zmvh[r * 72 + c] = *(const uint4*)&g_Wzmvh[g];
            *(uint4*)&zmvl[r * 72 + c] = *(const uint4*)&g_Wzmvl[g];
            *(uint4*)&amvh[r * 72 + c] = *(const uint4*)&g_Wamvh[g];
            *(uint4*)&amvl[r * 72 + c] = *(const uint4*)&g_Wamvl[g];
        }
        __syncthreads();

        // MMA1: gate_pre = c0 @ Wm1chunk   (K=128)
        float gatec[16];
#pragma unroll
        for (int i = 0; i < 16; i++) gatec[i] = 0.f;
        mma_gemm<2, 8>(gatec, aC0H, aC0L, bWm1H, bWm1L, 144);

        // elementwise: mempre = mv * sigmoid(gate_pre + bm1)
#pragma unroll
        for (int t = 0; t < 4; t++) {
            int cc = wc * 32 + t * 8 + 2 * (lane & 3);   // chunk-local col (even)
            int gcol = mch * 64 + cc;
            float b0 = bm1[gcol], b1 = bm1[gcol + 1];
#pragma unroll
            for (int half = 0; half < 2; half++) {
                int rl = wr * 16 + (lane >> 2) + half * 8;
                int r  = row0 + rl;
                int i0 = t * 4 + half * 2;
                float2 m2 = *(const float2*)&mv[(size_t)r * kMV + gcol];
                float p0 = m2.x * sgm(gatec[i0 + 0] + b0);
                float p1 = m2.y * sgm(gatec[i0 + 1] + b1);
                float2 pw; pw.x = p0; pw.y = p1;
                *(float2*)&g_mempre[(size_t)r * kMV + gcol] = pw;
                __nv_bfloat16 h0,l0,h1,l1;
                splitf(p0, h0, l0); splitf(p1, h1, l1);
                __nv_bfloat162 ph; ph.x = h0; ph.y = h1;
                __nv_bfloat162 pl; pl.x = l0; pl.y = l1;
                *(__nv_bfloat162*)&mph[rl * 72 + cc] = ph;
                *(__nv_bfloat162*)&mpl[rl * 72 + cc] = pl;
            }
        }
        __syncthreads();

        // MMA2: acc{e,z,a} += mempre @ W*mv chunk   (K=64)
        mma_gemm<2, 4>(acce, aMPH, aMPL, bEmvH, bEmvL, 144);
        mma_gemm<2, 4>(accz, aMPH, aMPL, bZmvH, bZmvL, 144);
        mma_gemm<2, 4>(acca, aMPH, aMPL, bAmvH, bAmvL, 144);
    }

    // ---- tail GEMMs via MMA ----
    __syncthreads();
#pragma unroll
    for (int i = 0; i < 2; i++) {                        // We [128][64] -> wm1 region
        int e = tid + i * 512;
        int r = e >> 3, c = (e & 7) * 8;
        *(uint4*)&wm1h[r * 72 + c] = *(const uint4*)&g_Weh[(size_t)r * kDV + c];
        *(uint4*)&wm1l[r * 72 + c] = *(const uint4*)&g_Wel[(size_t)r * kDV + c];
    }
    __syncthreads();
    float tmp1[16], tmp2[16];
#pragma unroll
    for (int i = 0; i < 16; i++) tmp1[i] = 0.f;
    mma_gemm<2, 8>(tmp1, aC0H, aC0L, bWm1H, bWm1L, 144);    // e1p = c0 @ We
    __syncthreads();
#pragma unroll
    for (int i = 0; i < 2; i++) {                        // Wz [128][64] -> w3 region
        int e = tid + i * 512;
        int r = e >> 3, c = (e & 7) * 8;
        *(uint4*)&wzh[r * 72 + c] = *(const uint4*)&g_Wzh[(size_t)r * kDV + c];
        *(uint4*)&wzl[r * 72 + c] = *(const uint4*)&g_Wzl[(size_t)r * kDV + c];
    }
    __syncthreads();
#pragma unroll
    for (int i = 0; i < 16; i++) tmp2[i] = 0.f;
    mma_gemm<2, 8>(tmp2, aC0H, aC0L, bWzH, bWzL, 144);      // zcp = c0 @ Wz

    // erase -> es (We region dead); zt -> mph/mpl (mempre smem dead); load Wza
#pragma unroll
    for (int t = 0; t < 4; t++) {
        int c = wc * 32 + t * 8 + 2 * (lane & 3);
        float bev0 = be[c], bev1 = be[c+1], bmv0 = bemv[c], bmv1 = bemv[c+1];
        float bzv0 = bz[c], bzv1 = bz[c+1], bzm0 = bzmv[c], bzm1 = bzmv[c+1];
#pragma unroll
        for (int half = 0; half < 2; half++) {
            int rl = wr * 16 + (lane >> 2) + half * 8;
            int i0 = t * 4 + half * 2;
            es[rl * 68 + c    ] = sgm(sgm(tmp1[i0    ] + bev0) + sgm(acce[i0    ] + bmv0));
            es[rl * 68 + c + 1] = sgm(sgm(tmp1[i0 + 1] + bev1) + sgm(acce[i0 + 1] + bmv1));
            float z0 = sgm(tmp2[i0    ] + bzv0 + accz[i0    ] + bzm0);
            float z1 = sgm(tmp2[i0 + 1] + bzv1 + accz[i0 + 1] + bzm1);
            __nv_bfloat16 h0,l0,h1,l1;
            splitf(z0, h0, l0); splitf(z1, h1, l1);
            __nv_bfloat162 ph; ph.x = h0; ph.y = h1;
            __nv_bfloat162 pl; pl.x = l0; pl.y = l1;
            *(__nv_bfloat162*)&mph[rl * 72 + c] = ph;
            *(__nv_bfloat162*)&mpl[rl * 72 + c] = pl;
        }
    }
    {                                                    // Wza [64][64]
        int r = tid >> 3, c = (tid & 7) * 8;
        *(uint4*)&zah[r * 72 + c] = *(const uint4*)&g_Wzah[(size_t)r * kDV + c];
        *(uint4*)&zal[r * 72 + c] = *(const uint4*)&g_Wzal[(size_t)r * kDV + c];
    }
    __syncthreads();
#pragma unroll
    for (int i = 0; i < 16; i++) tmp1[i] = 0.f;
    mma_gemm<2, 4>(tmp1, aMPH, aMPL, bZaH, bZaL, 144);      // tap = zt @ Wza

    // add -> ad (Wz region dead; disjoint from zah/zal)
#pragma unroll
    for (int t = 0; t < 4; t++) {
        int c = wc * 32 + t * 8 + 2 * (lane & 3);
        float bza0 = bza[c], bza1 = bza[c+1], bam0 = bamv[c], bam1 = bamv[c+1];
#pragma unroll
        for (int half = 0; half < 2; half++) {
            int rl = wr * 16 + (lane >> 2) + half * 8;
            int i0 = t * 4 + half * 2;
            ad[rl * 68 + c    ] = tanhf(tanhf(tmp1[i0    ] + bza0) + tanhf(acca[i0    ] + bam0));
            ad[rl * 68 + c + 1] = tanhf(tanhf(tmp1[i0 + 1] + bza1) + tanhf(acca[i0 + 1] + bam1));
        }
    }
    __syncthreads();

    // ---- final combine: out = mempre*(1 - w*erase) + w*add ----
    {
        const int tx = tid & 15, ty = tid >> 4, col = tx * 4;
        float4 e4[4], a4f[4];
#pragma unroll
        for (int i = 0; i < 4; i++) {
            e4[i]  = *(float4*)&es[(ty * 4 + i) * 68 + col];
            a4f[i] = *(float4*)&ad[(ty * 4 + i) * 68 + col];
        }
        for (int mm = 0; mm < kM; mm++) {
#pragma unroll
            for (int i = 0; i < 4; i++) {
                int r = row0 + ty * 4 + i;
                float ww = g_w[r * kM + mm];
                float4 mp = *(float4*)&g_mempre[(size_t)r * kMV + mm * 64 + col];
                float4 o;
                o.x = mp.x * (1.f - ww * e4[i].x) + ww * a4f[i].x;
                o.y = mp.y * (1.f - ww * e4[i].y) + ww * a4f[i].y;
                o.z = mp.z * (1.f - ww * e4[i].z) + ww * a4f[i].z;
                o.w = mp.w * (1.f - ww * e4[i].w) + ww * a4f[i].w;
                *(float4*)&out[(size_t)r * kMV + mm * 64 + col] = o;
            }
        }
    }
}

extern "C" void kernel_launch(void* const* d_in, const int* in_sizes, int n_in,
                              void* d_out, int out_size)
{
    const float* ck   = (const float*)d_in[0];
    const float* qa   = (const float*)d_in[1];
    const float* mk   = (const float*)d_in[2];
    const float* mv   = (const float*)d_in[3];
    const float* We   = (const float*)d_in[4];
    const float* be   = (const float*)d_in[5];
    const float* Wemv = (const float*)d_in[6];
    const float* bemv = (const float*)d_in[7];
    const float* Wza  = (const float*)d_in[8];
    const float* bza  = (const float*)d_in[9];
    const float* Wamv = (const float*)d_in[10];
    const float* bamv = (const float*)d_in[11];
    const float* Wc0  = (const float*)d_in[12];
    const float* bc0  = (const float*)d_in[13];
    const float* Wm1  = (const float*)d_in[14];
    const float* bm1  = (const float*)d_in[15];
    const float* Wz   = (const float*)d_in[16];
    const float* bz   = (const float*)d_in[17];
    const float* Wzmv = (const float*)d_in[18];
    const float* bzmv = (const float*)d_in[19];

    const int smem1 = 17920 * 4;   // 71680 B
    const int smem2 = 49664 * 4;   // 198656 B
    cudaFuncSetAttribute(k1_kernel, cudaFuncAttributeMaxDynamicSharedMemorySize, smem1);
    cudaFuncSetAttribute(k2_kernel, cudaFuncAttributeMaxDynamicSharedMemorySize, smem2);

    k0_convert<<<1024, 512>>>(Wc0, Wm1, Wemv, Wzmv, Wamv, We, Wz, Wza);
    k1_kernel<<<kB / 128, 512, smem1>>>(ck, qa, mk, mv, bc0);
    k2_kernel<<<kB / 128, 512, smem2>>>(mv, be, bemv, bza, bamv, bm1, bz, bzmv,
                                        (float*)d_out);
}